// round 3
// baseline (speedup 1.0000x reference)
#include <cuda_runtime.h>
#include <cuda_bf16.h>
#include <stdint.h>

// SimpleMovingAverage: history (64, 336, 862, 3) f32.
// window = last Q=12 steps; 336 iterations of m = mean(window, axis=time),
// window = shift-in(m). Output (64, 336, 862, 3).
//
// Each (b, station, channel) scalar series is independent. Use a running-sum
// sliding window: m = S/12; S += m - w[oldest]; w[oldest] = m. Unroll the
// time loop by 12 so the ring-buffer index is compile-time static (registers,
// not local memory).
//
// Vectorize by float2 along the contiguous (station*channel)=2586 axis
// (2586 % 2 == 0; % 4 != 0 so float4 would straddle rows).

#define SMA_Q       12
#define SMA_INLEN   336
#define SMA_OUTLEN  336
#define SMA_ROW     2586          // 862 * 3 floats, contiguous
#define SMA_ROW2    (SMA_ROW / 2) // 1293 float2 per row
#define SMA_BATCH   64
#define SMA_NTHREADS (SMA_BATCH * SMA_ROW2)  // 82752

__global__ __launch_bounds__(256, 8)
void sma_kernel(const float* __restrict__ in, float* __restrict__ out) {
    int id = blockIdx.x * blockDim.x + threadIdx.x;
    if (id >= SMA_NTHREADS) return;

    int b  = id / SMA_ROW2;
    int j2 = id - b * SMA_ROW2;

    const float2* __restrict__ src =
        reinterpret_cast<const float2*>(
            in + (size_t)b * SMA_INLEN * SMA_ROW
               + (size_t)(SMA_INLEN - SMA_Q) * SMA_ROW) + j2;
    float2* __restrict__ dst =
        reinterpret_cast<float2*>(out + (size_t)b * SMA_OUTLEN * SMA_ROW) + j2;

    // Load the 12-deep window for this (b, j2) lane pair; build running sum.
    float2 w[SMA_Q];
    float sx = 0.0f, sy = 0.0f;
#pragma unroll
    for (int k = 0; k < SMA_Q; k++) {
        w[k] = src[(size_t)k * SMA_ROW2];
        sx += w[k].x;
        sy += w[k].y;
    }

    const float inv_q = 1.0f / (float)SMA_Q;

    // 336 = 28 * 12: outer loop dynamic, inner fully unrolled so the
    // ring-buffer slot u is a compile-time register index.
    float2* d = dst;
#pragma unroll 1
    for (int t = 0; t < SMA_OUTLEN; t += SMA_Q) {
#pragma unroll
        for (int u = 0; u < SMA_Q; u++) {
            float mx = sx * inv_q;
            float my = sy * inv_q;
            d[(size_t)u * SMA_ROW2] = make_float2(mx, my);
            sx += mx - w[u].x;
            sy += my - w[u].y;
            w[u].x = mx;
            w[u].y = my;
        }
        d += (size_t)SMA_Q * SMA_ROW2;
    }
}

extern "C" void kernel_launch(void* const* d_in, const int* in_sizes, int n_in,
                              void* d_out, int out_size) {
    (void)in_sizes; (void)n_in; (void)out_size;
    const float* in = (const float*)d_in[0];
    float* out = (float*)d_out;

    const int threads = 256;
    const int blocks = (SMA_NTHREADS + threads - 1) / threads;  // 324
    sma_kernel<<<blocks, threads>>>(in, out);
}

// round 4
// speedup vs baseline: 1.6676x; 1.6676x over previous
#include <cuda_runtime.h>
#include <cuda_bf16.h>
#include <stdint.h>

// SimpleMovingAverage: history (64, 336, 862, 3) f32.
// window = last Q=12 steps; 336 iterations of m = mean(window, axis=time),
// push m into window. Output (64, 336, 862, 3).
//
// Per-series sliding running sum, with the recurrence collapsed to a single
// FFMA on the critical path:
//   m_t = s_t / 12
//   s_{t+1} = s_t + m_t - w_old = fma(s_t, 13/12, -w_old)
// Ring buffer index made compile-time static by unrolling the time loop by 12
// (336 = 28 * 12) so the window lives entirely in registers.
//
// R2 lesson: __launch_bounds__(256,8) capped regs at 32 and spilled the
// 24-register window to local memory (L1 55% busy, DRAM 25%). Occupancy is
// grid-limited (2586 warps total), so no min-blocks clause here.

#define SMA_Q       12
#define SMA_INLEN   336
#define SMA_OUTLEN  336
#define SMA_ROW     2586          // 862 * 3 floats, contiguous
#define SMA_ROW2    (SMA_ROW / 2) // 1293 float2 per row
#define SMA_BATCH   64
#define SMA_NTHREADS (SMA_BATCH * SMA_ROW2)  // 82752

__global__ __launch_bounds__(128)
void sma_kernel(const float* __restrict__ in, float* __restrict__ out) {
    int id = blockIdx.x * blockDim.x + threadIdx.x;
    if (id >= SMA_NTHREADS) return;

    int b  = id / SMA_ROW2;
    int j2 = id - b * SMA_ROW2;

    const float2* __restrict__ src =
        reinterpret_cast<const float2*>(
            in + (size_t)b * SMA_INLEN * SMA_ROW
               + (size_t)(SMA_INLEN - SMA_Q) * SMA_ROW) + j2;
    float2* __restrict__ dst =
        reinterpret_cast<float2*>(out + (size_t)b * SMA_OUTLEN * SMA_ROW) + j2;

    // Load the 12-deep window for this (b, j2) lane pair; build running sum.
    float2 w[SMA_Q];
    float sx = 0.0f, sy = 0.0f;
#pragma unroll
    for (int k = 0; k < SMA_Q; k++) {
        w[k] = src[(size_t)k * SMA_ROW2];
        sx += w[k].x;
        sy += w[k].y;
    }

    const float inv_q   = 1.0f / 12.0f;
    const float k1312   = 13.0f / 12.0f;

    float2* d = dst;
#pragma unroll 1
    for (int t = 0; t < SMA_OUTLEN; t += SMA_Q) {
#pragma unroll
        for (int u = 0; u < SMA_Q; u++) {
            // off-critical-path: the mean to store / to push into the window
            float mx = sx * inv_q;
            float my = sy * inv_q;
            d[(size_t)u * SMA_ROW2] = make_float2(mx, my);
            // critical path: single FFMA per component
            sx = fmaf(sx, k1312, -w[u].x);
            sy = fmaf(sy, k1312, -w[u].y);
            w[u].x = mx;
            w[u].y = my;
        }
        d += (size_t)SMA_Q * SMA_ROW2;
    }
}

extern "C" void kernel_launch(void* const* d_in, const int* in_sizes, int n_in,
                              void* d_out, int out_size) {
    (void)in_sizes; (void)n_in; (void)out_size;
    const float* in = (const float*)d_in[0];
    float* out = (float*)d_out;

    const int threads = 128;
    const int blocks = (SMA_NTHREADS + threads - 1) / threads;  // 647
    sma_kernel<<<blocks, threads>>>(in, out);
}